// round 2
// baseline (speedup 1.0000x reference)
#include <cuda_runtime.h>
#include <stdint.h>

#define T_SEQ 2048
#define BATCH 64
#define INPUT 16
#define HEADS 8
#define HID   64
#define GATES 256   // 4*HID

// 2048*64*8*64 floats = 268 MB scratch for per-step hidden states
__device__ float g_hs[T_SEQ * BATCH * HEADS * HID];

#define FMA2(acc, a, b) \
    asm("fma.rn.f32x2 %0, %1, %2, %0;" : "+l"(acc) : "l"(a), "l"(b))
#define ADD2(d, a, b) \
    asm("add.rn.f32x2 %0, %1, %2;" : "=l"(d) : "l"(a), "l"(b))
#define PACK2(d, lo, hi) \
    asm("mov.b64 %0, {%1, %2};" : "=l"(d) : "f"(lo), "f"(hi))
#define UNPACK2(lo, hi, s) \
    asm("mov.b64 {%0, %1}, %2;" : "=f"(lo), "=f"(hi) : "l"(s))

__device__ __forceinline__ float fsigmoid(float x) {
    float e = __expf(-x);
    return __fdividef(1.0f, 1.0f + e);
}
__device__ __forceinline__ float ftanh_fast(float x) {
    float e = __expf(-2.0f * x);
    return __fdividef(2.0f, 1.0f + e) - 1.0f;
}

// One CTA per (head, batch-pair): 2 independent chains sharing weights.
// 256 threads; thread g owns gate row g of both chains.
__global__ __launch_bounds__(256, 2)
void lstm_chain2_kernel(const float* __restrict__ x,
                        const float* __restrict__ W_ih,
                        const float* __restrict__ W_hh,
                        const float* __restrict__ b_ih,
                        const float* __restrict__ b_hh) {
    const int h  = blockIdx.x & 7;
    const int b0 = (blockIdx.x >> 3) * 2;
    const int g  = threadIdx.x;

    __shared__ __align__(16) float sh_h[2][HID];
    __shared__ __align__(16) float sh_x[2][INPUT];
    __shared__ float sh_act[2][GATES];

    // Pack weights for this gate row into 64-bit f32x2 registers (once).
    uint64_t w[HID / 2];   // 32
    uint64_t xw[INPUT / 2]; // 8
    {
        const float* wr = W_hh + (h * GATES + g) * HID;
#pragma unroll
        for (int q = 0; q < HID / 2; q++) PACK2(w[q], wr[2 * q], wr[2 * q + 1]);
        const float* xr = W_ih + (h * GATES + g) * INPUT;
#pragma unroll
        for (int q = 0; q < INPUT / 2; q++) PACK2(xw[q], xr[2 * q], xr[2 * q + 1]);
    }
    const float bias = b_ih[h * GATES + g] + b_hh[h * GATES + g];
    uint64_t bias2; PACK2(bias2, bias, 0.0f);

    float c0 = 0.0f, c1 = 0.0f;
    if (g < HID)  { sh_h[0][g] = 0.0f; sh_h[1][g] = 0.0f; }
    if (g < 32)   { int ch = g >> 4; sh_x[ch][g & 15] = x[(b0 + ch) * INPUT + (g & 15)]; }
    __syncthreads();

    const int gate_type = g >> 6;  // warp-uniform: 0:i 1:f 2:g 3:o

#pragma unroll 1
    for (int t = 0; t < T_SEQ; t++) {
        // Prefetch next x for both chains
        float xreg = 0.0f;
        if (g < 32 && t + 1 < T_SEQ) {
            int ch = g >> 4;
            xreg = x[((t + 1) * BATCH + b0 + ch) * INPUT + (g & 15)];
        }

        // z = bias + W_ih.x_t + W_hh.h_prev  (packed f32x2, both chains)
        uint64_t a00 = bias2, a01 = 0ull, a02 = 0ull, a03 = 0ull;
        uint64_t a10 = bias2, a11 = 0ull, a12 = 0ull, a13 = 0ull;

        const ulonglong2* x20 = (const ulonglong2*)sh_x[0];
        const ulonglong2* x21 = (const ulonglong2*)sh_x[1];
#pragma unroll
        for (int q = 0; q < INPUT / 4; q++) {   // 4 iters, 2 pairs each
            ulonglong2 v0 = x20[q], v1 = x21[q];
            FMA2(a00, xw[2 * q],     v0.x);
            FMA2(a01, xw[2 * q + 1], v0.y);
            FMA2(a10, xw[2 * q],     v1.x);
            FMA2(a11, xw[2 * q + 1], v1.y);
        }
        const ulonglong2* h20 = (const ulonglong2*)sh_h[0];
        const ulonglong2* h21 = (const ulonglong2*)sh_h[1];
#pragma unroll
        for (int q = 0; q < HID / 4; q++) {     // 16 iters, 2 pairs each
            ulonglong2 v0 = h20[q], v1 = h21[q];
            FMA2(a02, w[2 * q],     v0.x);
            FMA2(a03, w[2 * q + 1], v0.y);
            FMA2(a12, w[2 * q],     v1.x);
            FMA2(a13, w[2 * q + 1], v1.y);
        }

        uint64_t s0, t0, s1, t1;
        ADD2(s0, a00, a01); ADD2(t0, a02, a03); ADD2(s0, s0, t0);
        ADD2(s1, a10, a11); ADD2(t1, a12, a13); ADD2(s1, s1, t1);
        float lo0, hi0, lo1, hi1;
        UNPACK2(lo0, hi0, s0);
        UNPACK2(lo1, hi1, s1);
        float z0 = lo0 + hi0;
        float z1 = lo1 + hi1;

        float act0 = (gate_type == 2) ? ftanh_fast(z0) : fsigmoid(z0);
        float act1 = (gate_type == 2) ? ftanh_fast(z1) : fsigmoid(z1);
        sh_act[0][g] = act0;
        sh_act[1][g] = act1;
        __syncthreads();   // B1: acts visible; reads of sh_h/sh_x complete

        if (g < HID) {
            float iv0 = sh_act[0][g], fv0 = sh_act[0][HID + g];
            float gv0 = sh_act[0][2 * HID + g], ov0 = sh_act[0][3 * HID + g];
            float iv1 = sh_act[1][g], fv1 = sh_act[1][HID + g];
            float gv1 = sh_act[1][2 * HID + g], ov1 = sh_act[1][3 * HID + g];
            c0 = fmaf(fv0, c0, iv0 * gv0);
            c1 = fmaf(fv1, c1, iv1 * gv1);
            float h0v = ov0 * ftanh_fast(c0);
            float h1v = ov1 * ftanh_fast(c1);
            sh_h[0][g] = h0v;
            sh_h[1][g] = h1v;
            g_hs[((t * BATCH + b0) * HEADS + h) * HID + g]     = h0v;
            g_hs[((t * BATCH + b0 + 1) * HEADS + h) * HID + g] = h1v;
        }
        if (g < 32) sh_x[g >> 4][g & 15] = xreg;
        __syncthreads();   // B2: new sh_h/sh_x visible
    }
}

// Finalize: out[t,b,h] = hs[t,b,h,:].W_lin[h] + b_lin[h];
//           lstm_out[t,b,k] = sum_h hs[t,b,h,k]
// Block of 256 threads handles 4 (t,b) pairs; out-reduction via shuffles.
__global__ __launch_bounds__(256)
void finalize_kernel(const float* __restrict__ W_lin,
                     const float* __restrict__ b_lin,
                     float* __restrict__ out,
                     float* __restrict__ lstm_out) {
    const int local = threadIdx.x >> 6;   // 0..3 (tb within block)
    const int k     = threadIdx.x & 63;
    const int wsub  = (threadIdx.x >> 5) & 1;  // warp half within the 64-group
    const int tb    = blockIdx.x * 4 + local;

    __shared__ float red[4][2][HEADS];

    const float* hp = g_hs + (size_t)tb * (HEADS * HID);
    float p[HEADS];
    float s = 0.0f;
#pragma unroll
    for (int h = 0; h < HEADS; h++) {
        float v = hp[h * HID + k];
        s += v;
        p[h] = v * W_lin[h * HID + k];
    }
    lstm_out[(size_t)tb * HID + k] = s;

    // intra-warp reduction of the 8 per-head partials
#pragma unroll
    for (int lvl = 16; lvl >= 1; lvl >>= 1)
#pragma unroll
        for (int h = 0; h < HEADS; h++)
            p[h] += __shfl_xor_sync(0xffffffffu, p[h], lvl);

    if ((threadIdx.x & 31) == 0)
#pragma unroll
        for (int h = 0; h < HEADS; h++) red[local][wsub][h] = p[h];
    __syncthreads();

    if (threadIdx.x < 32) {
        const int l2 = threadIdx.x >> 3;   // 0..3
        const int h  = threadIdx.x & 7;
        float acc = red[l2][0][h] + red[l2][1][h] + b_lin[h];
        out[(size_t)(blockIdx.x * 4 + l2) * HEADS + h] = acc;
    }
}

extern "C" void kernel_launch(void* const* d_in, const int* in_sizes, int n_in,
                              void* d_out, int out_size) {
    const float* x     = (const float*)d_in[0];  // (T,B,I)
    const float* W_ih  = (const float*)d_in[1];  // (H,4h,I)
    const float* W_hh  = (const float*)d_in[2];  // (H,4h,h)
    const float* b_ih  = (const float*)d_in[3];  // (H,4h)
    const float* b_hh  = (const float*)d_in[4];  // (H,4h)
    const float* W_lin = (const float*)d_in[5];  // (H,h)
    const float* b_lin = (const float*)d_in[6];  // (H,)

    float* out      = (float*)d_out;                          // (T,B,H)
    float* lstm_out = out + (size_t)T_SEQ * BATCH * HEADS;    // (T,B,hid)

    lstm_chain2_kernel<<<BATCH * HEADS / 2, 256>>>(x, W_ih, W_hh, b_ih, b_hh);
    finalize_kernel<<<(T_SEQ * BATCH) / 4, 256>>>(W_lin, b_lin, out, lstm_out);
}

// round 4
// speedup vs baseline: 1.3144x; 1.3144x over previous
#include <cuda_runtime.h>
#include <stdint.h>

#define T_SEQ 2048
#define BATCH 64
#define INPUT 16
#define HEADS 8
#define HID   64
#define GATES 256   // 4*HID

#define FMA2(acc, a, b) \
    asm("fma.rn.f32x2 %0, %1, %2, %0;" : "+l"(acc) : "l"(a), "l"(b))
#define ADD2(d, a, b) \
    asm("add.rn.f32x2 %0, %1, %2;" : "=l"(d) : "l"(a), "l"(b))
#define PACK2(d, lo, hi) \
    asm("mov.b64 %0, {%1, %2};" : "=l"(d) : "f"(lo), "f"(hi))
#define UNPACK2(lo, hi, s) \
    asm("mov.b64 {%0, %1}, %2;" : "=f"(lo), "=f"(hi) : "l"(s))

__device__ __forceinline__ float fsigmoid(float x) {
    float e = __expf(-x);
    return __fdividef(1.0f, 1.0f + e);
}
__device__ __forceinline__ float ftanh_fast(float x) {
    float e = __expf(-2.0f * x);
    return __fdividef(2.0f, 1.0f + e) - 1.0f;
}

// Pre-fill outputs: out[t,b,h] = b_lin[h]; lstm_out = 0. (d_out is poisoned.)
__global__ __launch_bounds__(256)
void init_out_kernel(const float* __restrict__ b_lin, float* __restrict__ o) {
    const int idx = blockIdx.x * 256 + threadIdx.x;
    const int n_out = T_SEQ * BATCH * HEADS;
    const int n_tot = n_out + T_SEQ * BATCH * HID;
    if (idx < n_out)      o[idx] = b_lin[idx & 7];
    else if (idx < n_tot) o[idx] = 0.0f;
}

// One CTA per (batch, head) chain. 256 threads; thread g owns gate row g.
// Outputs fused: per step, lanes g<64 REDG-accumulate into out and lstm_out.
__global__ __launch_bounds__(256, 2)
void lstm_chain_kernel(const float* __restrict__ x,
                       const float* __restrict__ W_ih,
                       const float* __restrict__ W_hh,
                       const float* __restrict__ b_ih,
                       const float* __restrict__ b_hh,
                       const float* __restrict__ W_lin,
                       float* __restrict__ out,       // (T,B,H)
                       float* __restrict__ lstm_out)  // (T,B,HID)
{
    const int b = blockIdx.x >> 3;
    const int h = blockIdx.x & 7;
    const int g = threadIdx.x;

    __shared__ __align__(16) float sh_h[HID];
    __shared__ __align__(16) float sh_x[INPUT];
    __shared__ float sh_act[GATES];

    // Pack weights for this gate row into f32x2 registers (once).
    uint64_t w[HID / 2];    // 32 u64 = 64 regs
    uint64_t xw[INPUT / 2]; // 8 u64  = 16 regs
    {
        const float* wr = W_hh + (h * GATES + g) * HID;
#pragma unroll
        for (int q = 0; q < HID / 2; q++) PACK2(w[q], wr[2 * q], wr[2 * q + 1]);
        const float* xr = W_ih + (h * GATES + g) * INPUT;
#pragma unroll
        for (int q = 0; q < INPUT / 2; q++) PACK2(xw[q], xr[2 * q], xr[2 * q + 1]);
    }
    const float bias = b_ih[h * GATES + g] + b_hh[h * GATES + g];
    uint64_t bias2; PACK2(bias2, bias, 0.0f);

    // Per-head linear weight for this hidden unit (lanes g<64 only)
    const float wl = (g < HID) ? W_lin[h * HID + g] : 0.0f;

    float c = 0.0f;
    if (g < HID)   sh_h[g] = 0.0f;
    if (g < INPUT) sh_x[g] = x[b * INPUT + g];   // x[t=0, b, :]
    __syncthreads();

    const int gate_type = g >> 6;  // warp-uniform: 0:i 1:f 2:g 3:o

    float* out_p  = out + (size_t)b * HEADS + h;          // += t*B*H per step
    float* lstm_p = lstm_out + (size_t)b * HID + (g & 63);

#pragma unroll 1
    for (int t = 0; t < T_SEQ; t++) {
        // Prefetch next x (latency hidden under the matvec)
        float xreg = 0.0f;
        if (g < INPUT && t + 1 < T_SEQ)
            xreg = x[((t + 1) * BATCH + b) * INPUT + g];

        // z = bias + W_ih[g,:].x_t + W_hh[g,:].h_prev  (packed f32x2)
        uint64_t a0 = bias2, a1 = 0ull, a2 = 0ull, a3 = 0ull;
        const ulonglong2* x2 = (const ulonglong2*)sh_x;
#pragma unroll
        for (int q = 0; q < INPUT / 4; q++) {
            ulonglong2 v = x2[q];
            FMA2(a0, xw[2 * q],     v.x);
            FMA2(a1, xw[2 * q + 1], v.y);
        }
        const ulonglong2* h2 = (const ulonglong2*)sh_h;
#pragma unroll
        for (int q = 0; q < HID / 4; q++) {
            ulonglong2 v = h2[q];
            FMA2(a2, w[2 * q],     v.x);
            FMA2(a3, w[2 * q + 1], v.y);
        }
        uint64_t s, u;
        ADD2(s, a0, a1); ADD2(u, a2, a3); ADD2(s, s, u);
        float lo, hi;
        UNPACK2(lo, hi, s);
        float z = lo + hi;

        float a = (gate_type == 2) ? ftanh_fast(z) : fsigmoid(z);
        sh_act[g] = a;
        __syncthreads();   // B1: acts visible; reads of sh_h/sh_x complete

        if (g < HID) {
            float iv = sh_act[g];
            float fv = sh_act[HID + g];
            float gv = sh_act[2 * HID + g];
            float ov = sh_act[3 * HID + g];
            c = fmaf(fv, c, iv * gv);
            float hv = ov * ftanh_fast(c);
            sh_h[g] = hv;
            // Fused epilogue: no hs materialization.
            atomicAdd(out_p,  hv * wl);   // RED.ADD.F32, 64 lanes -> 1 addr
            atomicAdd(lstm_p, hv);        // 8 head-CTAs -> same addr
        }
        if (g < INPUT) sh_x[g] = xreg;
        __syncthreads();   // B2: new sh_h/sh_x visible

        out_p  += BATCH * HEADS;
        lstm_p += BATCH * HID;
    }
}

extern "C" void kernel_launch(void* const* d_in, const int* in_sizes, int n_in,
                              void* d_out, int out_size) {
    const float* x     = (const float*)d_in[0];  // (T,B,I)
    const float* W_ih  = (const float*)d_in[1];  // (H,4h,I)
    const float* W_hh  = (const float*)d_in[2];  // (H,4h,h)
    const float* b_ih  = (const float*)d_in[3];  // (H,4h)
    const float* b_hh  = (const float*)d_in[4];  // (H,4h)
    const float* W_lin = (const float*)d_in[5];  // (H,h)
    const float* b_lin = (const float*)d_in[6];  // (H,)

    float* out      = (float*)d_out;                          // (T,B,H)
    float* lstm_out = out + (size_t)T_SEQ * BATCH * HEADS;    // (T,B,hid)

    const int n_tot = T_SEQ * BATCH * (HEADS + HID);
    init_out_kernel<<<(n_tot + 255) / 256, 256>>>(b_lin, (float*)d_out);
    lstm_chain_kernel<<<BATCH * HEADS, 256>>>(x, W_ih, W_hh, b_ih, b_hh,
                                              W_lin, out, lstm_out);
}